// round 1
// baseline (speedup 1.0000x reference)
#include <cuda_runtime.h>

// Problem constants
#define T 4
#define BATCH 16
#define C 512
#define NPIX 1024          // H*W = 32*32
#define HEADS 8
#define EPSBN 1e-5f

// GEMM tiling
#define BM 64
#define BN 64
#define KC 16

// Scratch: binary spike maps stored as bytes (allowed: __device__ globals)
__device__ unsigned char g_xs  [T * BATCH * C * NPIX];       // 33.5 MB
__device__ unsigned char g_q   [T * BATCH * C * NPIX];       // 33.5 MB
__device__ unsigned char g_k   [T * BATCH * C * NPIX];       // 33.5 MB
__device__ unsigned char g_attn[T * BATCH * HEADS * NPIX];   // 0.5 MB

// ---------------------------------------------------------------------------
// Kernel 1: LIF over input x  ->  xs (binary, uint8)
// v' = 0.5*v + 0.5*x ; s = (v' >= 1) ; v = s ? 0 : v'
// ---------------------------------------------------------------------------
__global__ void lif_x_kernel(const float* __restrict__ x) {
    const int tot = BATCH * C * NPIX / 4;       // float4 granularity
    int idx = blockIdx.x * blockDim.x + threadIdx.x;
    if (idx >= tot) return;
    float v0 = 0.f, v1 = 0.f, v2 = 0.f, v3 = 0.f;
#pragma unroll
    for (int t = 0; t < T; t++) {
        float4 xv = reinterpret_cast<const float4*>(x)[idx + t * tot];
        uchar4 o;
        v0 = 0.5f * (v0 + xv.x); o.x = (v0 >= 1.f); if (o.x) v0 = 0.f;
        v1 = 0.5f * (v1 + xv.y); o.y = (v1 >= 1.f); if (o.y) v1 = 0.f;
        v2 = 0.5f * (v2 + xv.z); o.z = (v2 >= 1.f); if (o.z) v2 = 0.f;
        v3 = 0.5f * (v3 + xv.w); o.w = (v3 >= 1.f); if (o.w) v3 = 0.f;
        reinterpret_cast<uchar4*>(g_xs)[idx + t * tot] = o;
    }
}

// ---------------------------------------------------------------------------
// Kernel 2: q/k path:  spikes = LIF( BN( W @ xs ) ), all T accumulated in regs
// Block: 64(d) x 64(n) tile, one b; 256 threads; micro 4d x 4n x 4t per thread
// ---------------------------------------------------------------------------
__global__ __launch_bounds__(256, 1) void qk_gemm_kernel(
    const float* __restrict__ W,
    const float* __restrict__ gamma, const float* __restrict__ beta,
    const float* __restrict__ mean,  const float* __restrict__ var,
    int which)
{
    __shared__ float Ws[KC][BM];
    __shared__ float Xs[KC][T][BN];
    unsigned char* __restrict__ outspk = which ? g_k : g_q;

    const int b  = blockIdx.z;
    const int d0 = blockIdx.y * BM;
    const int n0 = blockIdx.x * BN;
    const int tid = threadIdx.x;
    const int tx = tid & 15;          // n group
    const int ty = tid >> 4;          // d group

    float acc[T][4][4];
#pragma unroll
    for (int t = 0; t < T; t++)
#pragma unroll
        for (int i = 0; i < 4; i++)
#pragma unroll
            for (int j = 0; j < 4; j++) acc[t][i][j] = 0.f;

    for (int k0 = 0; k0 < C; k0 += KC) {
        // Load W tile (64d x 16c), transpose into Ws[kk][d]
        {
            int d  = tid >> 2;
            int c4 = (tid & 3) * 4;
            float4 w = *reinterpret_cast<const float4*>(&W[(d0 + d) * C + k0 + c4]);
            Ws[c4 + 0][d] = w.x; Ws[c4 + 1][d] = w.y;
            Ws[c4 + 2][d] = w.z; Ws[c4 + 3][d] = w.w;
        }
        // Load xs tile: 16c x 4t x 64n bytes -> floats
#pragma unroll
        for (int i = 0; i < 4; i++) {
            int e  = tid + i * 256;       // 0..1023
            int n4 = e & 15;
            int t  = (e >> 4) & 3;
            int kk = e >> 6;
            uchar4 u = *reinterpret_cast<const uchar4*>(
                &g_xs[(((t * BATCH + b) * C) + (k0 + kk)) * NPIX + n0 + n4 * 4]);
            float* dst = &Xs[kk][t][n4 * 4];
            dst[0] = u.x; dst[1] = u.y; dst[2] = u.z; dst[3] = u.w;
        }
        __syncthreads();
#pragma unroll
        for (int kk = 0; kk < KC; kk++) {
            float a[4];
            *reinterpret_cast<float4*>(a) =
                *reinterpret_cast<const float4*>(&Ws[kk][ty * 4]);
            float bb[T][4];
#pragma unroll
            for (int t = 0; t < T; t++)
                *reinterpret_cast<float4*>(bb[t]) =
                    *reinterpret_cast<const float4*>(&Xs[kk][t][tx * 4]);
#pragma unroll
            for (int t = 0; t < T; t++)
#pragma unroll
                for (int i = 0; i < 4; i++)
#pragma unroll
                    for (int j = 0; j < 4; j++)
                        acc[t][i][j] = fmaf(a[i], bb[t][j], acc[t][i][j]);
        }
        __syncthreads();
    }

    // Epilogue: BN then LIF across T, write binary spikes
#pragma unroll
    for (int i = 0; i < 4; i++) {
        int d = d0 + ty * 4 + i;
        float inv = gamma[d] * rsqrtf(var[d] + EPSBN);
        float bsh = beta[d] - mean[d] * inv;
        float spk[T][4];
#pragma unroll
        for (int j = 0; j < 4; j++) {
            float v = 0.f;
#pragma unroll
            for (int t = 0; t < T; t++) {
                float val = fmaf(acc[t][i][j], inv, bsh);
                v = 0.5f * (v + val);
                float s = (v >= 1.0f) ? 1.f : 0.f;
                spk[t][j] = s;
                if (s != 0.f) v = 0.f;
            }
        }
#pragma unroll
        for (int t = 0; t < T; t++) {
            uchar4 u;
            u.x = (unsigned char)spk[t][0];
            u.y = (unsigned char)spk[t][1];
            u.z = (unsigned char)spk[t][2];
            u.w = (unsigned char)spk[t][3];
            *reinterpret_cast<uchar4*>(
                &outspk[((t * BATCH + b) * C + d) * NPIX + n0 + tx * 4]) = u;
        }
    }
}

// ---------------------------------------------------------------------------
// Kernel 3: head-sum of q + LIF(vth=0.5) -> attn (uint8 scratch + fp32 output)
// ---------------------------------------------------------------------------
__global__ void attn_kernel(float* __restrict__ attn_out) {
    int idx = blockIdx.x * blockDim.x + threadIdx.x;   // B*HEADS*NPIX/4 threads
    int n4 = idx & (NPIX / 4 - 1);
    int bh = idx >> 8;                 // NPIX/4 == 256
    int b = bh >> 3, h = bh & 7;
    float v0 = 0.f, v1 = 0.f, v2 = 0.f, v3 = 0.f;
#pragma unroll
    for (int t = 0; t < T; t++) {
        float s0 = 0.f, s1 = 0.f, s2 = 0.f, s3 = 0.f;
        const unsigned char* base =
            &g_q[(((t * BATCH + b) * C) + h * 64) * NPIX + n4 * 4];
#pragma unroll 8
        for (int dh = 0; dh < 64; dh++) {
            uchar4 u = *reinterpret_cast<const uchar4*>(base + dh * NPIX);
            s0 += u.x; s1 += u.y; s2 += u.z; s3 += u.w;
        }
        uchar4 o; float4 f;
        v0 = 0.5f * (v0 + s0); o.x = (v0 >= 0.5f); f.x = (float)o.x; if (o.x) v0 = 0.f;
        v1 = 0.5f * (v1 + s1); o.y = (v1 >= 0.5f); f.y = (float)o.y; if (o.y) v1 = 0.f;
        v2 = 0.5f * (v2 + s2); o.z = (v2 >= 0.5f); f.z = (float)o.z; if (o.z) v2 = 0.f;
        v3 = 0.5f * (v3 + s3); o.w = (v3 >= 0.5f); f.w = (float)o.w; if (o.w) v3 = 0.f;
        int oi = ((t * BATCH + b) * HEADS + h) * NPIX + n4 * 4;
        *reinterpret_cast<uchar4*>(&g_attn[oi]) = o;
        *reinterpret_cast<float4*>(&attn_out[oi]) = f;
    }
}

// ---------------------------------------------------------------------------
// Kernel 4: out = BN( proj_w @ (attn ⊙ k) + proj_b ); attn⊙k formed on load
// ---------------------------------------------------------------------------
__global__ __launch_bounds__(256, 1) void proj_gemm_kernel(
    const float* __restrict__ W, const float* __restrict__ bias,
    const float* __restrict__ gamma, const float* __restrict__ beta,
    const float* __restrict__ mean,  const float* __restrict__ var,
    float* __restrict__ out)
{
    __shared__ float Ws[KC][BM];
    __shared__ float Xs[KC][T][BN];

    const int b  = blockIdx.z;
    const int d0 = blockIdx.y * BM;
    const int n0 = blockIdx.x * BN;
    const int tid = threadIdx.x;
    const int tx = tid & 15;
    const int ty = tid >> 4;

    float acc[T][4][4];
#pragma unroll
    for (int t = 0; t < T; t++)
#pragma unroll
        for (int i = 0; i < 4; i++)
#pragma unroll
            for (int j = 0; j < 4; j++) acc[t][i][j] = 0.f;

    for (int k0 = 0; k0 < C; k0 += KC) {
        {
            int d  = tid >> 2;
            int c4 = (tid & 3) * 4;
            float4 w = *reinterpret_cast<const float4*>(&W[(d0 + d) * C + k0 + c4]);
            Ws[c4 + 0][d] = w.x; Ws[c4 + 1][d] = w.y;
            Ws[c4 + 2][d] = w.z; Ws[c4 + 3][d] = w.w;
        }
#pragma unroll
        for (int i = 0; i < 4; i++) {
            int e  = tid + i * 256;
            int n4 = e & 15;
            int t  = (e >> 4) & 3;
            int kk = e >> 6;
            int c  = k0 + kk;
            uchar4 kv = *reinterpret_cast<const uchar4*>(
                &g_k[(((t * BATCH + b) * C) + c) * NPIX + n0 + n4 * 4]);
            uchar4 av = *reinterpret_cast<const uchar4*>(
                &g_attn[(((t * BATCH + b) * HEADS) + (c >> 6)) * NPIX + n0 + n4 * 4]);
            float* dst = &Xs[kk][t][n4 * 4];
            dst[0] = (float)(kv.x & av.x);
            dst[1] = (float)(kv.y & av.y);
            dst[2] = (float)(kv.z & av.z);
            dst[3] = (float)(kv.w & av.w);
        }
        __syncthreads();
#pragma unroll
        for (int kk = 0; kk < KC; kk++) {
            float a[4];
            *reinterpret_cast<float4*>(a) =
                *reinterpret_cast<const float4*>(&Ws[kk][ty * 4]);
            float bb[T][4];
#pragma unroll
            for (int t = 0; t < T; t++)
                *reinterpret_cast<float4*>(bb[t]) =
                    *reinterpret_cast<const float4*>(&Xs[kk][t][tx * 4]);
#pragma unroll
            for (int t = 0; t < T; t++)
#pragma unroll
                for (int i = 0; i < 4; i++)
#pragma unroll
                    for (int j = 0; j < 4; j++)
                        acc[t][i][j] = fmaf(a[i], bb[t][j], acc[t][i][j]);
        }
        __syncthreads();
    }

    // Epilogue: BN of (conv + bias), fp32 output
#pragma unroll
    for (int i = 0; i < 4; i++) {
        int d = d0 + ty * 4 + i;
        float inv = gamma[d] * rsqrtf(var[d] + EPSBN);
        float bsh = beta[d] - mean[d] * inv + bias[d] * inv;
#pragma unroll
        for (int t = 0; t < T; t++) {
            float4 o;
            o.x = fmaf(acc[t][i][0], inv, bsh);
            o.y = fmaf(acc[t][i][1], inv, bsh);
            o.z = fmaf(acc[t][i][2], inv, bsh);
            o.w = fmaf(acc[t][i][3], inv, bsh);
            *reinterpret_cast<float4*>(
                &out[((t * BATCH + b) * C + d) * NPIX + n0 + tx * 4]) = o;
        }
    }
}

// ---------------------------------------------------------------------------
extern "C" void kernel_launch(void* const* d_in, const int* in_sizes, int n_in,
                              void* d_out, int out_size) {
    const float* x      = (const float*)d_in[0];
    const float* q_w    = (const float*)d_in[1];
    const float* q_g    = (const float*)d_in[2];
    const float* q_b    = (const float*)d_in[3];
    const float* q_m    = (const float*)d_in[4];
    const float* q_v    = (const float*)d_in[5];
    const float* k_w    = (const float*)d_in[6];
    const float* k_g    = (const float*)d_in[7];
    const float* k_b    = (const float*)d_in[8];
    const float* k_m    = (const float*)d_in[9];
    const float* k_v    = (const float*)d_in[10];
    const float* p_w    = (const float*)d_in[11];
    const float* p_bias = (const float*)d_in[12];
    const float* p_g    = (const float*)d_in[13];
    const float* p_b    = (const float*)d_in[14];
    const float* p_m    = (const float*)d_in[15];
    const float* p_v    = (const float*)d_in[16];
    float* out = (float*)d_out;

    // 1) input LIF -> binary xs
    lif_x_kernel<<<(BATCH * C * NPIX / 4 + 255) / 256, 256>>>(x);

    // 2) q and k paths (GEMM + BN + LIF fused)
    dim3 gg(NPIX / BN, C / BM, BATCH);
    qk_gemm_kernel<<<gg, 256>>>(q_w, q_g, q_b, q_m, q_v, 0);
    qk_gemm_kernel<<<gg, 256>>>(k_w, k_g, k_b, k_m, k_v, 1);

    // 3) head-sum + LIF(0.5) -> attn (also written to fp32 output region)
    attn_kernel<<<(BATCH * HEADS * NPIX / 4) / 256, 256>>>(
        out + (size_t)T * BATCH * C * NPIX);

    // 4) proj GEMM on (attn & k) + bias + BN -> fp32 output
    proj_gemm_kernel<<<gg, 256>>>(p_w, p_bias, p_g, p_b, p_m, p_v, out);
}